// round 9
// baseline (speedup 1.0000x reference)
#include <cuda_runtime.h>
#include <cuda_fp16.h>
#include <cstdint>

// Problem dims
#define BATCH 8192
#define IN    1024
#define OUT   1024

// GEMM tiling: block 128x128, 8 warps (2M x 4N), warp tile 64x32, fp16.
// K-chunk per stage = 128 halves (two 64-half sub-tiles), 8 k16 steps/stage.
#define BM 128
#define BN 128
#define KCH 128           // K-halves per stage
#define SUBH 64           // halves per sub-tile row (= 128 bytes)
#define KT (IN / KCH)     // 8 k-iterations
#define STAGES 3
#define THREADS 256

#define A_STAGE_HALVES (BM * KCH)           // 16384 halves = 32 KB
#define B_STAGE_HALVES (BN * KCH)
#define A_SUB_BYTES (BM * SUBH * 2)         // 16384 B
#define B_SUB_BYTES (BN * SUBH * 2)
#define A_STAGE_BYTES (A_STAGE_HALVES * 2)  // 32768 B
#define B_STAGE_BYTES (B_STAGE_HALVES * 2)

// Scratch: fp16-rounded operands, K-contiguous
__device__ __half g_weffh[OUT * IN];   // [O, I]
__device__ __half g_xrh[BATCH * IN];   // [B, I]

// ---------------------------------------------------------------------------
// Helpers
// ---------------------------------------------------------------------------
__device__ __forceinline__ uint32_t h2_bits(__half2 h) {
    return *reinterpret_cast<uint32_t*>(&h);
}
__device__ __forceinline__ void cp_async16(void* s, const void* g) {
    uint32_t sa = (uint32_t)__cvta_generic_to_shared(s);
    asm volatile("cp.async.cg.shared.global [%0], [%1], 16;\n" :: "r"(sa), "l"(g));
}
__device__ __forceinline__ void cp_commit() {
    asm volatile("cp.async.commit_group;\n");
}
__device__ __forceinline__ void cp_wait1() {
    asm volatile("cp.async.wait_group 1;\n");
}
__device__ __forceinline__ void ldsm_x4(uint32_t* r, uint32_t saddr) {
    asm volatile("ldmatrix.sync.aligned.m8n8.x4.shared.b16 {%0,%1,%2,%3}, [%4];"
        : "=r"(r[0]), "=r"(r[1]), "=r"(r[2]), "=r"(r[3]) : "r"(saddr));
}
// fp16 MMA, fp32 accumulate: D[16x8] += A[16x16] * B[16x8]
__device__ __forceinline__ void mma_f16(float* c, const uint32_t* a, const uint32_t* b) {
    asm volatile(
        "mma.sync.aligned.m16n8k16.row.col.f32.f16.f16.f32 "
        "{%0,%1,%2,%3},{%4,%5,%6,%7},{%8,%9},{%0,%1,%2,%3};\n"
        : "+f"(c[0]), "+f"(c[1]), "+f"(c[2]), "+f"(c[3])
        : "r"(a[0]), "r"(a[1]), "r"(a[2]), "r"(a[3]), "r"(b[0]), "r"(b[1]));
}

// ---------------------------------------------------------------------------
// Kernel A (prep): round x -> g_xrh (fp16-rn), build+round w_eff -> g_weffh
// ---------------------------------------------------------------------------
__global__ void prep_kernel(const float4* __restrict__ x4,
                            const float4* __restrict__ coef,
                            const float* __restrict__ w) {
    const int NXH = BATCH * IN / 8;          // 1M: each handles 8 floats of x
    int idx = blockIdx.x * blockDim.x + threadIdx.x;
    if (idx < NXH) {
        float4 v0 = x4[2 * idx];
        float4 v1 = x4[2 * idx + 1];
        uint4 out;
        out.x = h2_bits(__floats2half2_rn(v0.x, v0.y));
        out.y = h2_bits(__floats2half2_rn(v0.z, v0.w));
        out.z = h2_bits(__floats2half2_rn(v1.x, v1.y));
        out.w = h2_bits(__floats2half2_rn(v1.z, v1.w));
        reinterpret_cast<uint4*>(g_xrh)[idx] = out;
    } else {
        int i = (idx - NXH) * 2;             // 2 w_eff elements per thread
        float r0, r1;
        {
            float4 c0 = coef[2 * i];
            float4 c1 = coef[2 * i + 1];
            float s = ((c0.x + c0.y) + (c0.z + c0.w)) + ((c1.x + c1.y) + (c1.z + c1.w));
            r0 = s * w[i];
        }
        {
            float4 c0 = coef[2 * (i + 1)];
            float4 c1 = coef[2 * (i + 1) + 1];
            float s = ((c0.x + c0.y) + (c0.z + c0.w)) + ((c1.x + c1.y) + (c1.z + c1.w));
            r1 = s * w[i + 1];
        }
        reinterpret_cast<uint32_t*>(g_weffh)[i / 2] = h2_bits(__floats2half2_rn(r0, r1));
    }
}

// ---------------------------------------------------------------------------
// Kernel B: C[8192,1024] = Xh @ Weffh^T  (TN, fp16 mma.sync + ldmatrix,
//           8 big stages, register-double-buffered fragments)
// ---------------------------------------------------------------------------
// Sub-tile rows: 128 bytes (64 halves), 8 x 16B groups, swizzle group^=(row&7).
// Stage layout: [A sub0 | A sub1] then (in B region) [B sub0 | B sub1].
__device__ __forceinline__ void load_stage(const __half* __restrict__ Ag,
                                           const __half* __restrict__ Bg,
                                           __half* as, __half* bs,
                                           int kt, int lr, int lc) {
#pragma unroll
    for (int sub = 0; sub < 2; sub++) {
        int kofs = kt * KCH + sub * SUBH + lc * 8;   // half index within K
        __half* asub = as + sub * BM * SUBH;
        __half* bsub = bs + sub * BN * SUBH;
#pragma unroll
        for (int j = 0; j < 4; j++) {                // 128 rows / 32 per pass
            int r = lr + j * 32;
            int sw = (lc ^ (r & 7)) * 8;             // halves
            cp_async16(asub + r * SUBH + sw, Ag + (size_t)r * IN + kofs);
            cp_async16(bsub + r * SUBH + sw, Bg + (size_t)r * IN + kofs);
        }
    }
}

__global__ void __launch_bounds__(THREADS, 1)
gemm_f16(const __half* __restrict__ A, float* __restrict__ C) {
    extern __shared__ __half smem[];
    __half* As = smem;                            // STAGES * A_STAGE_HALVES
    __half* Bs = smem + STAGES * A_STAGE_HALVES;  // STAGES * B_STAGE_HALVES

    const int tid    = threadIdx.x;
    const int warpId = tid >> 5;              // 0..7
    const int lane   = tid & 31;
    const int g      = lane >> 2;   // 0..7
    const int t4     = lane & 3;    // 0..3
    const int warpM  = warpId & 1;  // 2 warps in M (64 rows each)
    const int warpN  = warpId >> 1; // 4 warps in N (32 cols each)

    const int bm = blockIdx.y * BM;
    const int bn = blockIdx.x * BN;

    const int lr = tid >> 3;   // 0..31
    const int lc = tid & 7;    // 0..7

    const __half* Ag = A + (size_t)bm * IN;
    const __half* Bg = g_weffh + (size_t)bn * IN;

    // ldmatrix per-lane byte offsets within a sub-tile.
    const int j8 = lane >> 3;   // which 8x8 matrix of the x4
    const int rw = lane & 7;    // row within it
    uint32_t a_off[4], b_off[2];
#pragma unroll
    for (int mi = 0; mi < 4; mi++) {
        int row = warpM * 64 + mi * 16 + (j8 & 1) * 8 + rw;
        int c   = j8 >> 1;                   // k-half within step
        a_off[mi] = row * 128 + ((c ^ (row & 7)) * 16);
    }
#pragma unroll
    for (int nj = 0; nj < 2; nj++) {
        int n = warpN * 32 + nj * 16 + (j8 >> 1) * 8 + rw;
        int c = j8 & 1;
        b_off[nj] = n * 128 + ((c ^ (n & 7)) * 16);
    }
    const uint32_t smem_base = (uint32_t)__cvta_generic_to_shared(smem);
    const uint32_t b_region  = smem_base + STAGES * A_STAGE_BYTES;

    // Warp tile 64x32: 4 M-frags x 4 N-frags
    float acc[4][4][4];
#pragma unroll
    for (int mi = 0; mi < 4; mi++)
#pragma unroll
        for (int ni = 0; ni < 4; ni++)
#pragma unroll
            for (int k = 0; k < 4; k++) acc[mi][ni][k] = 0.f;

    // Prologue: stages 0,1
    load_stage(Ag, Bg, As + 0 * A_STAGE_HALVES, Bs + 0 * B_STAGE_HALVES, 0, lr, lc);
    cp_commit();
    load_stage(Ag, Bg, As + 1 * A_STAGE_HALVES, Bs + 1 * B_STAGE_HALVES, 1, lr, lc);
    cp_commit();

    for (int kt = 0; kt < KT; kt++) {
        cp_wait1();            // stage kt resident (kt+1 in flight)
        __syncthreads();       // stage (kt+2)%3 fully consumed (in iter kt-1)

        const uint32_t a_base = smem_base + (kt % STAGES) * A_STAGE_BYTES;
        const uint32_t b_base = b_region  + (kt % STAGES) * B_STAGE_BYTES;

        // Step-0 fragments first so MMAs can restart ASAP after the barrier.
        uint32_t af[2][4][4];
        uint32_t bf[2][4][2];
#pragma unroll
        for (int mi = 0; mi < 4; mi++)
            ldsm_x4(af[0][mi], a_base + a_off[mi]);
#pragma unroll
        for (int nj = 0; nj < 2; nj++) {
            uint32_t r[4];
            ldsm_x4(r, b_base + b_off[nj]);
            bf[0][2 * nj][0]     = r[0];
            bf[0][2 * nj][1]     = r[1];
            bf[0][2 * nj + 1][0] = r[2];
            bf[0][2 * nj + 1][1] = r[3];
        }

        // Then issue the global->smem prefetch for stage kt+2.
        if (kt + 2 < KT) {
            int s = (kt + 2) % STAGES;
            load_stage(Ag, Bg, As + s * A_STAGE_HALVES, Bs + s * B_STAGE_HALVES,
                       kt + 2, lr, lc);
        }
        cp_commit();           // keep group accounting uniform

#pragma unroll
        for (int s = 0; s < 8; s++) {        // eight k16 steps per stage
            const int cur = s & 1;
            const int nxt = cur ^ 1;
            if (s < 7) {
                const int sn = s + 1;
                const uint32_t sx   = (uint32_t)(sn & 3) * 32;
                const uint32_t asub = a_base + (sn >> 2) * A_SUB_BYTES;
                const uint32_t bsub = b_base + (sn >> 2) * B_SUB_BYTES;
#pragma unroll
                for (int mi = 0; mi < 4; mi++)
                    ldsm_x4(af[nxt][mi], asub + (a_off[mi] ^ sx));
#pragma unroll
                for (int nj = 0; nj < 2; nj++) {
                    uint32_t r[4];
                    ldsm_x4(r, bsub + (b_off[nj] ^ sx));
                    bf[nxt][2 * nj][0]     = r[0];
                    bf[nxt][2 * nj][1]     = r[1];
                    bf[nxt][2 * nj + 1][0] = r[2];
                    bf[nxt][2 * nj + 1][1] = r[3];
                }
            }
#pragma unroll
            for (int mi = 0; mi < 4; mi++)
#pragma unroll
                for (int ni = 0; ni < 4; ni++)
                    mma_f16(acc[mi][ni], af[cur][mi], bf[cur][ni]);
        }
    }

    // Epilogue: fp32 stores
#pragma unroll
    for (int mi = 0; mi < 4; mi++) {
#pragma unroll
        for (int ni = 0; ni < 4; ni++) {
            int row = bm + warpM * 64 + mi * 16 + g;
            int col = bn + warpN * 32 + ni * 8 + t4 * 2;
            float2 v01 = make_float2(acc[mi][ni][0], acc[mi][ni][1]);
            float2 v23 = make_float2(acc[mi][ni][2], acc[mi][ni][3]);
            *reinterpret_cast<float2*>(C + (size_t)row * OUT + col)       = v01;
            *reinterpret_cast<float2*>(C + (size_t)(row + 8) * OUT + col) = v23;
        }
    }
}

// ---------------------------------------------------------------------------
// Harness entry
// ---------------------------------------------------------------------------
extern "C" void kernel_launch(void* const* d_in, const int* in_sizes, int n_in,
                              void* d_out, int out_size) {
    const float4* x4   = (const float4*)d_in[0];  // [8192,1024] fp32
    const float4* coef = (const float4*)d_in[1];  // [1024,1024,8] fp32
    const float*  w    = (const float*)d_in[2];   // [1024,1024] fp32
    float* out = (float*)d_out;                   // [8192,1024] fp32
    (void)in_sizes; (void)n_in; (void)out_size;

    // Prep: 1M x-vector items + 512K w_eff pair items
    const int NXH = BATCH * IN / 8;               // 1M
    const int NPREP = NXH + OUT * IN / 2;         // 1.5M
    prep_kernel<<<(NPREP + 255) / 256, 256>>>(x4, coef, w);

    // fp16 GEMM, 192 KB smem, occ 1
    static const int smem_bytes = STAGES * (A_STAGE_BYTES + B_STAGE_BYTES); // 196608
    cudaFuncSetAttribute(gemm_f16, cudaFuncAttributeMaxDynamicSharedMemorySize, smem_bytes);

    const __half* xr_dev;
    cudaGetSymbolAddress((void**)&xr_dev, g_xrh);
    dim3 grid(OUT / BN, BATCH / BM);  // (8, 64)
    gemm_f16<<<grid, THREADS, smem_bytes>>>(xr_dev, out);
}

// round 10
// speedup vs baseline: 1.1648x; 1.1648x over previous
#include <cuda_runtime.h>
#include <cuda_fp16.h>
#include <cstdint>

// Problem dims
#define BATCH 8192
#define IN    1024
#define OUT   1024

// GEMM tiling: block 64x128, 4 warps (2M x 2N), warp tile 32x64, fp16
#define BM 64
#define BN 128
#define BKH 64            // K-halves per stage (= 128 bytes per row)
#define KT (IN / BKH)     // 16 k-iterations
#define STAGES 3
#define THREADS 128

#define A_STAGE_HALVES (BM * BKH)           // 4096 halves = 8 KB
#define B_STAGE_HALVES (BN * BKH)           // 8192 halves = 16 KB
#define A_STAGE_BYTES (A_STAGE_HALVES * 2)
#define B_STAGE_BYTES (B_STAGE_HALVES * 2)

// Scratch: fp16-rounded operands, K-contiguous
__device__ __half g_weffh[OUT * IN];   // [O, I]
__device__ __half g_xrh[BATCH * IN];   // [B, I]

// ---------------------------------------------------------------------------
// Helpers
// ---------------------------------------------------------------------------
__device__ __forceinline__ uint32_t h2_bits(__half2 h) {
    return *reinterpret_cast<uint32_t*>(&h);
}
__device__ __forceinline__ void cp_async16(void* s, const void* g) {
    uint32_t sa = (uint32_t)__cvta_generic_to_shared(s);
    asm volatile("cp.async.cg.shared.global [%0], [%1], 16;\n" :: "r"(sa), "l"(g));
}
__device__ __forceinline__ void cp_commit() {
    asm volatile("cp.async.commit_group;\n");
}
__device__ __forceinline__ void cp_wait1() {
    asm volatile("cp.async.wait_group 1;\n");
}
__device__ __forceinline__ void ldsm_x4(uint32_t* r, uint32_t saddr) {
    asm volatile("ldmatrix.sync.aligned.m8n8.x4.shared.b16 {%0,%1,%2,%3}, [%4];"
        : "=r"(r[0]), "=r"(r[1]), "=r"(r[2]), "=r"(r[3]) : "r"(saddr));
}
// fp16 MMA, fp32 accumulate: D[16x8] += A[16x16] * B[16x8]
__device__ __forceinline__ void mma_f16(float* c, const uint32_t* a, const uint32_t* b) {
    asm volatile(
        "mma.sync.aligned.m16n8k16.row.col.f32.f16.f16.f32 "
        "{%0,%1,%2,%3},{%4,%5,%6,%7},{%8,%9},{%0,%1,%2,%3};\n"
        : "+f"(c[0]), "+f"(c[1]), "+f"(c[2]), "+f"(c[3])
        : "r"(a[0]), "r"(a[1]), "r"(a[2]), "r"(a[3]), "r"(b[0]), "r"(b[1]));
}

// ---------------------------------------------------------------------------
// Kernel A (prep): round x -> g_xrh (fp16-rn), build+round w_eff -> g_weffh
// ---------------------------------------------------------------------------
__global__ void prep_kernel(const float4* __restrict__ x4,
                            const float4* __restrict__ coef,
                            const float* __restrict__ w) {
    const int NXH = BATCH * IN / 8;          // 1M: each handles 8 floats of x
    int idx = blockIdx.x * blockDim.x + threadIdx.x;
    if (idx < NXH) {
        float4 v0 = x4[2 * idx];
        float4 v1 = x4[2 * idx + 1];
        uint4 out;
        out.x = h2_bits(__floats2half2_rn(v0.x, v0.y));
        out.y = h2_bits(__floats2half2_rn(v0.z, v0.w));
        out.z = h2_bits(__floats2half2_rn(v1.x, v1.y));
        out.w = h2_bits(__floats2half2_rn(v1.z, v1.w));
        reinterpret_cast<uint4*>(g_xrh)[idx] = out;
    } else {
        int i = (idx - NXH) * 2;             // 2 w_eff elements per thread
        float r0, r1;
        {
            float4 c0 = coef[2 * i];
            float4 c1 = coef[2 * i + 1];
            float s = ((c0.x + c0.y) + (c0.z + c0.w)) + ((c1.x + c1.y) + (c1.z + c1.w));
            r0 = s * w[i];
        }
        {
            float4 c0 = coef[2 * (i + 1)];
            float4 c1 = coef[2 * (i + 1) + 1];
            float s = ((c0.x + c0.y) + (c0.z + c0.w)) + ((c1.x + c1.y) + (c1.z + c1.w));
            r1 = s * w[i + 1];
        }
        reinterpret_cast<uint32_t*>(g_weffh)[i / 2] = h2_bits(__floats2half2_rn(r0, r1));
    }
}

// ---------------------------------------------------------------------------
// Kernel B: C[8192,1024] = Xh @ Weffh^T  (TN, fp16 mma.sync + ldmatrix,
//           64x128 tiles, occ 3, register-double-buffered fragments)
// ---------------------------------------------------------------------------
// SMEM rows: 128 bytes (64 halves), 8 x 16B groups, swizzle group^=(row&7).
__device__ __forceinline__ void load_stage(const __half* __restrict__ Ag,
                                           const __half* __restrict__ Bg,
                                           __half* as, __half* bs,
                                           int kt, int lr, int lc) {
    int kofs = kt * BKH + lc * 8;            // half index within row
#pragma unroll
    for (int j = 0; j < 4; j++) {            // A: 64 rows / 16 per pass
        int r = lr + j * 16;
        int sw = (lc ^ (r & 7)) * 8;
        cp_async16(as + r * BKH + sw, Ag + (size_t)r * IN + kofs);
    }
#pragma unroll
    for (int j = 0; j < 8; j++) {            // B: 128 rows / 16 per pass
        int r = lr + j * 16;
        int sw = (lc ^ (r & 7)) * 8;
        cp_async16(bs + r * BKH + sw, Bg + (size_t)r * IN + kofs);
    }
}

__global__ void __launch_bounds__(THREADS, 3)
gemm_f16(const __half* __restrict__ A, float* __restrict__ C) {
    extern __shared__ __half smem[];
    __half* As = smem;                            // STAGES * A_STAGE_HALVES
    __half* Bs = smem + STAGES * A_STAGE_HALVES;  // STAGES * B_STAGE_HALVES

    const int tid    = threadIdx.x;
    const int warpId = tid >> 5;              // 0..3
    const int lane   = tid & 31;
    const int g      = lane >> 2;   // 0..7
    const int t4     = lane & 3;    // 0..3
    const int warpM  = warpId & 1;  // 2 warps in M (32 rows each)
    const int warpN  = warpId >> 1; // 2 warps in N (64 cols each)

    const int bm = blockIdx.y * BM;
    const int bn = blockIdx.x * BN;

    const int lr = tid >> 3;   // 0..15
    const int lc = tid & 7;    // 0..7

    const __half* Ag = A + (size_t)bm * IN;
    const __half* Bg = g_weffh + (size_t)bn * IN;

    // ldmatrix per-lane byte offsets (relative to stage A / stage B base).
    const int j8 = lane >> 3;   // which 8x8 matrix of the x4
    const int rw = lane & 7;    // row within it
    uint32_t a_off[2], b_off[4];
#pragma unroll
    for (int mi = 0; mi < 2; mi++) {
        int row = warpM * 32 + mi * 16 + (j8 & 1) * 8 + rw;
        int c   = j8 >> 1;                   // k-half within step
        a_off[mi] = row * 128 + ((c ^ (row & 7)) * 16);
    }
#pragma unroll
    for (int nj = 0; nj < 4; nj++) {
        int n = warpN * 64 + nj * 16 + (j8 >> 1) * 8 + rw;
        int c = j8 & 1;
        b_off[nj] = n * 128 + ((c ^ (n & 7)) * 16);
    }
    const uint32_t smem_base = (uint32_t)__cvta_generic_to_shared(smem);
    const uint32_t b_region  = smem_base + STAGES * A_STAGE_BYTES;

    // Warp tile 32x64: 2 M-frags x 8 N-frags
    float acc[2][8][4];
#pragma unroll
    for (int mi = 0; mi < 2; mi++)
#pragma unroll
        for (int ni = 0; ni < 8; ni++)
#pragma unroll
            for (int k = 0; k < 4; k++) acc[mi][ni][k] = 0.f;

    // Prologue: stages 0,1
    load_stage(Ag, Bg, As + 0 * A_STAGE_HALVES, Bs + 0 * B_STAGE_HALVES, 0, lr, lc);
    cp_commit();
    load_stage(Ag, Bg, As + 1 * A_STAGE_HALVES, Bs + 1 * B_STAGE_HALVES, 1, lr, lc);
    cp_commit();

    for (int kt = 0; kt < KT; kt++) {
        cp_wait1();            // stage kt resident (kt+1 in flight)
        __syncthreads();       // stage (kt+2)%3 fully consumed

        const uint32_t a_base = smem_base + (kt % STAGES) * A_STAGE_BYTES;
        const uint32_t b_base = b_region  + (kt % STAGES) * B_STAGE_BYTES;

        // Step-0 fragments first so MMAs restart ASAP after the barrier.
        uint32_t af[2][2][4];
        uint32_t bf[2][8][2];
#pragma unroll
        for (int mi = 0; mi < 2; mi++)
            ldsm_x4(af[0][mi], a_base + a_off[mi]);
#pragma unroll
        for (int nj = 0; nj < 4; nj++) {
            uint32_t r[4];
            ldsm_x4(r, b_base + b_off[nj]);
            bf[0][2 * nj][0]     = r[0];
            bf[0][2 * nj][1]     = r[1];
            bf[0][2 * nj + 1][0] = r[2];
            bf[0][2 * nj + 1][1] = r[3];
        }

        // Then issue the global->smem prefetch for stage kt+2.
        if (kt + 2 < KT) {
            int s = (kt + 2) % STAGES;
            load_stage(Ag, Bg, As + s * A_STAGE_HALVES, Bs + s * B_STAGE_HALVES,
                       kt + 2, lr, lc);
        }
        cp_commit();           // keep group accounting uniform

#pragma unroll
        for (int s = 0; s < 4; s++) {        // four k16 steps per stage
            const int cur = s & 1;
            const int nxt = cur ^ 1;
            if (s < 3) {
                const uint32_t sx = (uint32_t)(s + 1) * 32;
#pragma unroll
                for (int mi = 0; mi < 2; mi++)
                    ldsm_x4(af[nxt][mi], a_base + (a_off[mi] ^ sx));
#pragma unroll
                for (int nj = 0; nj < 4; nj++) {
                    uint32_t r[4];
                    ldsm_x4(r, b_base + (b_off[nj] ^ sx));
                    bf[nxt][2 * nj][0]     = r[0];
                    bf[nxt][2 * nj][1]     = r[1];
                    bf[nxt][2 * nj + 1][0] = r[2];
                    bf[nxt][2 * nj + 1][1] = r[3];
                }
            }
#pragma unroll
            for (int mi = 0; mi < 2; mi++)
#pragma unroll
                for (int ni = 0; ni < 8; ni++)
                    mma_f16(acc[mi][ni], af[cur][mi], bf[cur][ni]);
        }
    }

    // Epilogue: fp32 stores
#pragma unroll
    for (int mi = 0; mi < 2; mi++) {
#pragma unroll
        for (int ni = 0; ni < 8; ni++) {
            int row = bm + warpM * 32 + mi * 16 + g;
            int col = bn + warpN * 64 + ni * 8 + t4 * 2;
            float2 v01 = make_float2(acc[mi][ni][0], acc[mi][ni][1]);
            float2 v23 = make_float2(acc[mi][ni][2], acc[mi][ni][3]);
            *reinterpret_cast<float2*>(C + (size_t)row * OUT + col)       = v01;
            *reinterpret_cast<float2*>(C + (size_t)(row + 8) * OUT + col) = v23;
        }
    }
}

// ---------------------------------------------------------------------------
// Harness entry
// ---------------------------------------------------------------------------
extern "C" void kernel_launch(void* const* d_in, const int* in_sizes, int n_in,
                              void* d_out, int out_size) {
    const float4* x4   = (const float4*)d_in[0];  // [8192,1024] fp32
    const float4* coef = (const float4*)d_in[1];  // [1024,1024,8] fp32
    const float*  w    = (const float*)d_in[2];   // [1024,1024] fp32
    float* out = (float*)d_out;                   // [8192,1024] fp32
    (void)in_sizes; (void)n_in; (void)out_size;

    // Prep: 1M x-vector items + 512K w_eff pair items
    const int NXH = BATCH * IN / 8;               // 1M
    const int NPREP = NXH + OUT * IN / 2;         // 1.5M
    prep_kernel<<<(NPREP + 255) / 256, 256>>>(x4, coef, w);

    // fp16 GEMM, 72 KB smem, occ 3
    static const int smem_bytes = STAGES * (A_STAGE_BYTES + B_STAGE_BYTES); // 73728
    cudaFuncSetAttribute(gemm_f16, cudaFuncAttributeMaxDynamicSharedMemorySize, smem_bytes);

    const __half* xr_dev;
    cudaGetSymbolAddress((void**)&xr_dev, g_xrh);
    dim3 grid(OUT / BN, BATCH / BM);  // (8, 128) = 1024 CTAs
    gemm_f16<<<grid, THREADS, smem_bytes>>>(xr_dev, out);
}